// round 11
// baseline (speedup 1.0000x reference)
#include <cuda_runtime.h>

// ---------------------------------------------------------------------------
// StarLoss, single-launch, FENCE-FREE finalize.
//   loss = ( Sum(w1)*D1 + Sum(w2)*D2 + 0.5*Sum(trace) ) / M
// D1 = Sum p1^2, D2 = Sum p2^2 are global sums -> 5 streaming scalars.
// Traffic: 32 B/elem * 2^24 = 537 MB -> HBM-bound.
//
// Epilogue design (the hard-won part):
//  - R6/R8 lesson: __threadfence() is gpu-scope -> CCTL.IVALL (L1 flush) per
//    block. 4096 flushes cost ~12-18us. NEVER use threadfence here.
//  - R9 lesson: 5 shared-address FP64 atomics x all blocks finishing at once
//    serialize at the LTS ALU; separate finalize node costs 4.9us.
//  - Fix: per-block atomicExch (64-bit, bit-cast doubles) to PRIVATE slots
//    (no contention, bypasses L1, returns old value). The last-block ticket
//    atomicInc takes a wrap operand data-dependent on those returns
//    (laundered via asm), so the exchanges are COMPLETE at L2 before the
//    ticket issues -> correct ordering with no fence. Ticket self-resets on
//    wrap; slots fully overwritten each launch -> replay-deterministic with
//    zero init/reset kernels.
// ---------------------------------------------------------------------------

#define STAR_EPS 1e-5f
#define NBLOCKS  4096
#define NTHREADS 256

// per-block partials, stored as bit-cast doubles (atomicExch needs ull)
__device__ unsigned long long g_part[NBLOCKS][5];
__device__ unsigned int g_ticket = 0;     // self-resets via atomicInc wrap

__device__ __forceinline__ void star_elem(
    float a, float b, float d,
    float px, float py, float tx, float ty,
    float& acc_d1, float& acc_d2, float& acc_w1, float& acc_w2, float& acc_tr)
{
    float mean = 0.5f * (a + d);
    float h    = 0.5f * (a - d);
    float D2   = fmaf(h, h, b * b);
    float rin  = rsqrtf(D2);                 // MUFU.RSQ
    float delta = (D2 > 0.0f) ? D2 * rin : 0.0f;
    float lam1 = mean + delta;
    float lam2 = mean - delta;

    // eigenvector for lam1 (reference formula incl. diagonal fallback)
    bool diag = fabsf(b) < 1e-12f;
    bool ag   = (a >= d);
    float vx = diag ? (ag ? 1.0f : 0.0f) : b;
    float vy = diag ? (ag ? 0.0f : 1.0f) : (lam1 - a);
    float n2 = fmaf(vx, vx, vy * vy);
    float invn = rsqrtf(n2);                 // MUFU.RSQ
    float invn2 = invn * invn;

    float dx = px - tx;
    float dy = py - ty;
    float t1 = fmaf(vx, dx,  vy * dy);       //  v . r
    float t2 = fmaf(vx, dy, -vy * dx);       //  v_perp . r

    acc_d1 += t1 * t1 * invn2;
    acc_d2 += t2 * t2 * invn2;
    acc_w1 += rsqrtf(lam1) + STAR_EPS;       // lam1 >= 0.1 by construction
    acc_w2 += rsqrtf(lam2) + STAR_EPS;       // lam2 >= 0.1 by construction
    acc_tr += a + d;                          // lam1 + lam2 == trace
}

__global__ __launch_bounds__(NTHREADS)
void star_kernel(const float4* __restrict__ pred2,  // npairs float4 (2 elems)
                 const float4* __restrict__ cov,    // 2*npairs float4 (1 elem)
                 const float4* __restrict__ targ2,  // npairs float4
                 int npairs,
                 float* __restrict__ out,
                 double invM)
{
    float acc_d1 = 0.f, acc_d2 = 0.f, acc_w1 = 0.f, acc_w2 = 0.f, acc_tr = 0.f;

    int stride = gridDim.x * blockDim.x;
    #pragma unroll 2
    for (int i = blockIdx.x * blockDim.x + threadIdx.x; i < npairs; i += stride) {
        float4 p  = pred2[i];
        float4 t  = targ2[i];
        float4 c0 = cov[2 * i];
        float4 c1 = cov[2 * i + 1];
        // cov element layout: [a, b, b, d] -> .x, .y, .w
        star_elem(c0.x, c0.y, c0.w, p.x, p.y, t.x, t.y,
                  acc_d1, acc_d2, acc_w1, acc_w2, acc_tr);
        star_elem(c1.x, c1.y, c1.w, p.z, p.w, t.z, t.w,
                  acc_d1, acc_d2, acc_w1, acc_w2, acc_tr);
    }

    // ---- warp reduction ----
    #pragma unroll
    for (int off = 16; off > 0; off >>= 1) {
        acc_d1 += __shfl_down_sync(0xFFFFFFFFu, acc_d1, off);
        acc_d2 += __shfl_down_sync(0xFFFFFFFFu, acc_d2, off);
        acc_w1 += __shfl_down_sync(0xFFFFFFFFu, acc_w1, off);
        acc_w2 += __shfl_down_sync(0xFFFFFFFFu, acc_w2, off);
        acc_tr += __shfl_down_sync(0xFFFFFFFFu, acc_tr, off);
    }

    // ---- block reduction across 8 warps ----
    __shared__ float s[5][8];
    __shared__ bool s_last;
    int lane = threadIdx.x & 31;
    int wid  = threadIdx.x >> 5;
    if (lane == 0) {
        s[0][wid] = acc_d1; s[1][wid] = acc_d2;
        s[2][wid] = acc_w1; s[3][wid] = acc_w2; s[4][wid] = acc_tr;
    }
    __syncthreads();
    if (threadIdx.x == 0) {
        float v0 = 0.f, v1 = 0.f, v2 = 0.f, v3 = 0.f, v4 = 0.f;
        #pragma unroll
        for (int w = 0; w < NTHREADS / 32; w++) {
            v0 += s[0][w]; v1 += s[1][w]; v2 += s[2][w]; v3 += s[3][w]; v4 += s[4][w];
        }
        // Private-slot exchanges: contention-free, bypass L1, and the RETURNS
        // give us completion signals for fence-free ordering.
        unsigned long long r0 = atomicExch(&g_part[blockIdx.x][0],
                                           (unsigned long long)__double_as_longlong((double)v0));
        unsigned long long r1 = atomicExch(&g_part[blockIdx.x][1],
                                           (unsigned long long)__double_as_longlong((double)v1));
        unsigned long long r2 = atomicExch(&g_part[blockIdx.x][2],
                                           (unsigned long long)__double_as_longlong((double)v2));
        unsigned long long r3 = atomicExch(&g_part[blockIdx.x][3],
                                           (unsigned long long)__double_as_longlong((double)v3));
        unsigned long long r4 = atomicExch(&g_part[blockIdx.x][4],
                                           (unsigned long long)__double_as_longlong((double)v4));
        // Launder the returns into an always-zero term the compiler cannot
        // fold away: the ticket's wrap operand now DEPENDS on the exchange
        // results, so the warp waits for their completion before issuing it.
        unsigned lo = (unsigned)(r0 ^ r1 ^ r2 ^ r3 ^ r4);
        unsigned z;
        asm volatile("and.b32 %0, %1, 0;" : "=r"(z) : "r"(lo));
        unsigned old = atomicInc(&g_ticket, (NBLOCKS - 1u) + z);
        s_last = (old == NBLOCKS - 1u);   // ticket auto-reset to 0 on wrap
    }
    __syncthreads();

    // ---- last block finalizes (reads L2-resident partials, ~160KB) ----
    if (s_last) {
        double d0 = 0.0, d1 = 0.0, d2 = 0.0, d3 = 0.0, d4 = 0.0;
        for (int r = threadIdx.x; r < NBLOCKS; r += NTHREADS) {
            d0 += __longlong_as_double((long long)__ldcg(&g_part[r][0]));
            d1 += __longlong_as_double((long long)__ldcg(&g_part[r][1]));
            d2 += __longlong_as_double((long long)__ldcg(&g_part[r][2]));
            d3 += __longlong_as_double((long long)__ldcg(&g_part[r][3]));
            d4 += __longlong_as_double((long long)__ldcg(&g_part[r][4]));
        }
        #pragma unroll
        for (int off = 16; off > 0; off >>= 1) {
            d0 += __shfl_down_sync(0xFFFFFFFFu, d0, off);
            d1 += __shfl_down_sync(0xFFFFFFFFu, d1, off);
            d2 += __shfl_down_sync(0xFFFFFFFFu, d2, off);
            d3 += __shfl_down_sync(0xFFFFFFFFu, d3, off);
            d4 += __shfl_down_sync(0xFFFFFFFFu, d4, off);
        }
        __shared__ double sd[5][8];
        if (lane == 0) {
            sd[0][wid] = d0; sd[1][wid] = d1; sd[2][wid] = d2;
            sd[3][wid] = d3; sd[4][wid] = d4;
        }
        __syncthreads();
        if (threadIdx.x == 0) {
            double D1 = 0.0, D2s = 0.0, SW1 = 0.0, SW2 = 0.0, STR = 0.0;
            #pragma unroll
            for (int w = 0; w < NTHREADS / 32; w++) {
                D1 += sd[0][w]; D2s += sd[1][w]; SW1 += sd[2][w];
                SW2 += sd[3][w]; STR += sd[4][w];
            }
            // omega = 1.0 -> regularizer is 0.5 * trace
            out[0] = (float)((SW1 * D1 + SW2 * D2s + 0.5 * STR) * invM);
        }
    }
}

extern "C" void kernel_launch(void* const* d_in, const int* in_sizes, int n_in,
                              void* d_out, int out_size)
{
    const float4* pred2 = (const float4*)d_in[0];  // (B,N,2) f32
    const float4* cov   = (const float4*)d_in[1];  // (B,N,2,2) f32
    const float4* targ2 = (const float4*)d_in[2];  // (B,N,2) f32
    float* out = (float*)d_out;

    long long M = (long long)in_sizes[0] / 2;      // number of 2x2 problems
    int npairs  = (int)(M / 2);                    // two problems per pred float4

    star_kernel<<<NBLOCKS, NTHREADS>>>(pred2, cov, targ2, npairs,
                                       out, 1.0 / (double)M);
}

// round 13
// speedup vs baseline: 1.0914x; 1.0914x over previous
#include <cuda_runtime.h>

// ---------------------------------------------------------------------------
// StarLoss, 2-node graph: proven-fastest structure.
//   loss = ( Sum(w1)*D1 + Sum(w2)*D2 + 0.5*Sum(trace) ) / M
// D1 = Sum p1^2, D2 = Sum p2^2 are global sums -> 5 streaming scalars.
// Traffic: 32 B/elem * 2^24 = 537 MB -> HBM floor ~77 us.
//
// Measured design space (5 variants):
//   split + REDG atomicAdd + grid 4096  -> 86.5us  (BEST; main ~80us)
//   split + REDG atomicAdd + grid 1184  -> 89.1us  (single wave is WORSE)
//   fused epilogue (any flavor)         -> 94.7-100us (in-kernel finalize
//        keeps blocks resident through dependent L2 atomics; never again)
// This round: identical main kernel, zero-kernel merged into finalize
// (finalize self-resets g_acc after reading) -> 3 nodes become 2.
// ---------------------------------------------------------------------------

#define STAR_EPS 1e-5f
#define NBLOCKS  4096
#define NTHREADS 256

// [0]=D1, [1]=D2, [2]=Sum w1, [3]=Sum w2, [4]=Sum trace
// Zero at module load; finalize re-zeros after each consumption.
__device__ double g_acc[5] = {0.0, 0.0, 0.0, 0.0, 0.0};

__device__ __forceinline__ void star_elem(
    float a, float b, float d,
    float px, float py, float tx, float ty,
    float& acc_d1, float& acc_d2, float& acc_w1, float& acc_w2, float& acc_tr)
{
    float mean = 0.5f * (a + d);
    float h    = 0.5f * (a - d);
    float D2   = fmaf(h, h, b * b);
    float rin  = rsqrtf(D2);                 // MUFU.RSQ
    float delta = (D2 > 0.0f) ? D2 * rin : 0.0f;
    float lam1 = mean + delta;
    float lam2 = mean - delta;

    // eigenvector for lam1 (reference formula incl. diagonal fallback)
    bool diag = fabsf(b) < 1e-12f;
    bool ag   = (a >= d);
    float vx = diag ? (ag ? 1.0f : 0.0f) : b;
    float vy = diag ? (ag ? 0.0f : 1.0f) : (lam1 - a);
    float n2 = fmaf(vx, vx, vy * vy);
    float invn = rsqrtf(n2);                 // MUFU.RSQ
    float invn2 = invn * invn;

    float dx = px - tx;
    float dy = py - ty;
    float t1 = fmaf(vx, dx,  vy * dy);       //  v . r
    float t2 = fmaf(vx, dy, -vy * dx);       //  v_perp . r

    acc_d1 += t1 * t1 * invn2;
    acc_d2 += t2 * t2 * invn2;
    acc_w1 += rsqrtf(lam1) + STAR_EPS;       // lam1 >= 0.1 by construction
    acc_w2 += rsqrtf(lam2) + STAR_EPS;       // lam2 >= 0.1 by construction
    acc_tr += a + d;                          // lam1 + lam2 == trace
}

__global__ __launch_bounds__(NTHREADS)
void star_main_kernel(const float4* __restrict__ pred2,  // npairs float4 (2 elems)
                      const float4* __restrict__ cov,    // 2*npairs float4 (1 elem)
                      const float4* __restrict__ targ2,  // npairs float4
                      int npairs)
{
    float acc_d1 = 0.f, acc_d2 = 0.f, acc_w1 = 0.f, acc_w2 = 0.f, acc_tr = 0.f;

    int stride = gridDim.x * blockDim.x;
    #pragma unroll 2
    for (int i = blockIdx.x * blockDim.x + threadIdx.x; i < npairs; i += stride) {
        float4 p  = pred2[i];
        float4 t  = targ2[i];
        float4 c0 = cov[2 * i];
        float4 c1 = cov[2 * i + 1];
        // cov element layout: [a, b, b, d] -> .x, .y, .w
        star_elem(c0.x, c0.y, c0.w, p.x, p.y, t.x, t.y,
                  acc_d1, acc_d2, acc_w1, acc_w2, acc_tr);
        star_elem(c1.x, c1.y, c1.w, p.z, p.w, t.z, t.w,
                  acc_d1, acc_d2, acc_w1, acc_w2, acc_tr);
    }

    // ---- warp reduction ----
    #pragma unroll
    for (int off = 16; off > 0; off >>= 1) {
        acc_d1 += __shfl_down_sync(0xFFFFFFFFu, acc_d1, off);
        acc_d2 += __shfl_down_sync(0xFFFFFFFFu, acc_d2, off);
        acc_w1 += __shfl_down_sync(0xFFFFFFFFu, acc_w1, off);
        acc_w2 += __shfl_down_sync(0xFFFFFFFFu, acc_w2, off);
        acc_tr += __shfl_down_sync(0xFFFFFFFFu, acc_tr, off);
    }

    // ---- block reduction across 8 warps ----
    __shared__ float s[5][8];
    int lane = threadIdx.x & 31;
    int wid  = threadIdx.x >> 5;
    if (lane == 0) {
        s[0][wid] = acc_d1; s[1][wid] = acc_d2;
        s[2][wid] = acc_w1; s[3][wid] = acc_w2; s[4][wid] = acc_tr;
    }
    __syncthreads();
    if (threadIdx.x == 0) {
        float v0 = 0.f, v1 = 0.f, v2 = 0.f, v3 = 0.f, v4 = 0.f;
        #pragma unroll
        for (int w = 0; w < NTHREADS / 32; w++) {
            v0 += s[0][w]; v1 += s[1][w]; v2 += s[2][w]; v3 += s[3][w]; v4 += s[4][w];
        }
        // fire-and-forget REDG adds — the measured-fastest block exit
        atomicAdd(&g_acc[0], (double)v0);
        atomicAdd(&g_acc[1], (double)v1);
        atomicAdd(&g_acc[2], (double)v2);
        atomicAdd(&g_acc[3], (double)v3);
        atomicAdd(&g_acc[4], (double)v4);
    }
}

__global__ void star_finalize_kernel(float* __restrict__ out, double invM)
{
    if (threadIdx.x == 0) {
        double D1  = g_acc[0];
        double D2  = g_acc[1];
        double SW1 = g_acc[2];
        double SW2 = g_acc[3];
        double STR = g_acc[4];
        // omega = 1.0 -> regularizer term is 0.5 * trace
        out[0] = (float)((SW1 * D1 + SW2 * D2 + 0.5 * STR) * invM);
        // reset for the next graph replay (replaces the zero kernel)
        g_acc[0] = 0.0; g_acc[1] = 0.0; g_acc[2] = 0.0;
        g_acc[3] = 0.0; g_acc[4] = 0.0;
    }
}

extern "C" void kernel_launch(void* const* d_in, const int* in_sizes, int n_in,
                              void* d_out, int out_size)
{
    const float4* pred2 = (const float4*)d_in[0];  // (B,N,2) f32
    const float4* cov   = (const float4*)d_in[1];  // (B,N,2,2) f32
    const float4* targ2 = (const float4*)d_in[2];  // (B,N,2) f32
    float* out = (float*)d_out;

    long long M = (long long)in_sizes[0] / 2;      // number of 2x2 problems
    int npairs  = (int)(M / 2);                    // two problems per pred float4

    star_main_kernel<<<NBLOCKS, NTHREADS>>>(pred2, cov, targ2, npairs);
    star_finalize_kernel<<<1, 32>>>(out, 1.0 / (double)M);
}